// round 2
// baseline (speedup 1.0000x reference)
#include <cuda_runtime.h>
#include <float.h>

#define D 512
#define EPS 1e-5f

__device__ __forceinline__ float wsum(float v) {
#pragma unroll
    for (int o = 16; o; o >>= 1) v += __shfl_xor_sync(0xffffffffu, v, o);
    return v;
}
__device__ __forceinline__ float wmax(float v) {
#pragma unroll
    for (int o = 16; o; o >>= 1) v = fmaxf(v, __shfl_xor_sync(0xffffffffu, v, o));
    return v;
}

// One warp per row. Each lane owns 16 elements as 4 strided float4s
// (element block 4*(lane + 32*k)), fully coalesced 128B/warp accesses.
__global__ void __launch_bounds__(256, 8) simblock_kernel(
    const float* __restrict__ x, const float* __restrict__ y,
    const float* __restrict__ W1, const float* __restrict__ W2,
    const float* __restrict__ g1, const float* __restrict__ b1,
    const float* __restrict__ g2, const float* __restrict__ b2,
    float* __restrict__ out, int B)
{
    const int warp = (blockIdx.x * blockDim.x + threadIdx.x) >> 5;
    const int lane = threadIdx.x & 31;
    if (warp >= B) return;

    const float4* x4 = (const float4*)(x + (size_t)warp * D);
    const float4* y4 = (const float4*)(y + (size_t)warp * D);

    float4 xv[4], yv[4];
    float d1 = 0.f, d2 = 0.f;
#pragma unroll
    for (int k = 0; k < 4; k++) {
        const int idx = lane + 32 * k;
        xv[k] = x4[idx];
        yv[k] = y4[idx];
        const float4 w1 = __ldg((const float4*)W1 + idx);
        const float4 w2 = __ldg((const float4*)W2 + idx);
        d1 += yv[k].x * w1.x + yv[k].y * w1.y + yv[k].z * w1.z + yv[k].w * w1.w;
        d2 += yv[k].x * w2.x + yv[k].y * w2.y + yv[k].z * w2.z + yv[k].w * w2.w;
    }
    const float scale = rsqrtf((float)D);
    const float s1 = wsum(d1) * scale;
    const float s2 = wsum(d2) * scale;

    float* out_x = out + (size_t)warp * D;
    float* out_y = out + (size_t)(B + warp) * D;

    // ---------------- side X: softmax(x*s1)*x + x, then LN(g1,b1) ----------
    {
        float m = -FLT_MAX;
#pragma unroll
        for (int k = 0; k < 4; k++) {
            m = fmaxf(m, fmaxf(fmaxf(xv[k].x * s1, xv[k].y * s1),
                               fmaxf(xv[k].z * s1, xv[k].w * s1)));
        }
        m = wmax(m);

        float4 ov[4];
        float esum = 0.f;
#pragma unroll
        for (int k = 0; k < 4; k++) {
            ov[k].x = __expf(xv[k].x * s1 - m);
            ov[k].y = __expf(xv[k].y * s1 - m);
            ov[k].z = __expf(xv[k].z * s1 - m);
            ov[k].w = __expf(xv[k].w * s1 - m);
            esum += ov[k].x + ov[k].y + ov[k].z + ov[k].w;
        }
        esum = wsum(esum);
        const float inv_es = 1.0f / esum;

        float sum = 0.f, sumsq = 0.f;
#pragma unroll
        for (int k = 0; k < 4; k++) {
            ov[k].x = ov[k].x * inv_es * xv[k].x + xv[k].x;
            ov[k].y = ov[k].y * inv_es * xv[k].y + xv[k].y;
            ov[k].z = ov[k].z * inv_es * xv[k].z + xv[k].z;
            ov[k].w = ov[k].w * inv_es * xv[k].w + xv[k].w;
            sum   += ov[k].x + ov[k].y + ov[k].z + ov[k].w;
            sumsq += ov[k].x * ov[k].x + ov[k].y * ov[k].y
                   + ov[k].z * ov[k].z + ov[k].w * ov[k].w;
        }
        sum = wsum(sum);
        sumsq = wsum(sumsq);
        const float mu = sum * (1.0f / D);
        const float var = sumsq * (1.0f / D) - mu * mu;
        const float rstd = rsqrtf(var + EPS);
#pragma unroll
        for (int k = 0; k < 4; k++) {
            const int idx = lane + 32 * k;
            const float4 gg = __ldg((const float4*)g1 + idx);
            const float4 bb = __ldg((const float4*)b1 + idx);
            float4 r;
            r.x = (ov[k].x - mu) * rstd * gg.x + bb.x;
            r.y = (ov[k].y - mu) * rstd * gg.y + bb.y;
            r.z = (ov[k].z - mu) * rstd * gg.z + bb.z;
            r.w = (ov[k].w - mu) * rstd * gg.w + bb.w;
            ((float4*)out_x)[idx] = r;
        }
    }

    // ---------------- side Y: softmax(x*s2)*y + y, then LN(g2,b2) ----------
    {
        float m = -FLT_MAX;
#pragma unroll
        for (int k = 0; k < 4; k++) {
            m = fmaxf(m, fmaxf(fmaxf(xv[k].x * s2, xv[k].y * s2),
                               fmaxf(xv[k].z * s2, xv[k].w * s2)));
        }
        m = wmax(m);

        float4 ov[4];
        float esum = 0.f;
#pragma unroll
        for (int k = 0; k < 4; k++) {
            ov[k].x = __expf(xv[k].x * s2 - m);
            ov[k].y = __expf(xv[k].y * s2 - m);
            ov[k].z = __expf(xv[k].z * s2 - m);
            ov[k].w = __expf(xv[k].w * s2 - m);
            esum += ov[k].x + ov[k].y + ov[k].z + ov[k].w;
        }
        esum = wsum(esum);
        const float inv_es = 1.0f / esum;

        float sum = 0.f, sumsq = 0.f;
#pragma unroll
        for (int k = 0; k < 4; k++) {
            ov[k].x = ov[k].x * inv_es * yv[k].x + yv[k].x;
            ov[k].y = ov[k].y * inv_es * yv[k].y + yv[k].y;
            ov[k].z = ov[k].z * inv_es * yv[k].z + yv[k].z;
            ov[k].w = ov[k].w * inv_es * yv[k].w + yv[k].w;
            sum   += ov[k].x + ov[k].y + ov[k].z + ov[k].w;
            sumsq += ov[k].x * ov[k].x + ov[k].y * ov[k].y
                   + ov[k].z * ov[k].z + ov[k].w * ov[k].w;
        }
        sum = wsum(sum);
        sumsq = wsum(sumsq);
        const float mu = sum * (1.0f / D);
        const float var = sumsq * (1.0f / D) - mu * mu;
        const float rstd = rsqrtf(var + EPS);
#pragma unroll
        for (int k = 0; k < 4; k++) {
            const int idx = lane + 32 * k;
            const float4 gg = __ldg((const float4*)g2 + idx);
            const float4 bb = __ldg((const float4*)b2 + idx);
            float4 r;
            r.x = (ov[k].x - mu) * rstd * gg.x + bb.x;
            r.y = (ov[k].y - mu) * rstd * gg.y + bb.y;
            r.z = (ov[k].z - mu) * rstd * gg.z + bb.z;
            r.w = (ov[k].w - mu) * rstd * gg.w + bb.w;
            ((float4*)out_y)[idx] = r;
        }
    }
}

extern "C" void kernel_launch(void* const* d_in, const int* in_sizes, int n_in,
                              void* d_out, int out_size) {
    const float* x  = (const float*)d_in[0];
    const float* y  = (const float*)d_in[1];
    const float* W1 = (const float*)d_in[2];
    const float* W2 = (const float*)d_in[3];
    const float* g1 = (const float*)d_in[4];
    const float* b1 = (const float*)d_in[5];
    const float* g2 = (const float*)d_in[6];
    const float* b2 = (const float*)d_in[7];
    float* out = (float*)d_out;

    const int B = in_sizes[0] / D;           // 65536
    const int threads = 256;                 // 8 rows per block
    const int rows_per_block = threads / 32;
    const int blocks = (B + rows_per_block - 1) / rows_per_block;
    simblock_kernel<<<blocks, threads>>>(x, y, W1, W2, g1, b1, g2, b2, out, B);
}

// round 3
// speedup vs baseline: 2.3388x; 2.3388x over previous
#include <cuda_runtime.h>
#include <float.h>

#define D 512
#define EPS 1e-5f

__device__ __forceinline__ float wsum(float v) {
#pragma unroll
    for (int o = 16; o; o >>= 1) v += __shfl_xor_sync(0xffffffffu, v, o);
    return v;
}
__device__ __forceinline__ float wmax(float v) {
#pragma unroll
    for (int o = 16; o; o >>= 1) v = fmaxf(v, __shfl_xor_sync(0xffffffffu, v, o));
    return v;
}

// One warp per row. Each lane owns 16 elements as 4 strided float4s
// (element block 4*(lane + 32*k)), fully coalesced 128B/warp accesses.
// NOTE: min-blocks kept at 2 (128-reg budget) — R2 showed that forcing
// occupancy 8 caps regs at 32 and spills ~770MB to local memory.
__global__ void __launch_bounds__(256, 2) simblock_kernel(
    const float* __restrict__ x, const float* __restrict__ y,
    const float* __restrict__ W1, const float* __restrict__ W2,
    const float* __restrict__ g1, const float* __restrict__ b1,
    const float* __restrict__ g2, const float* __restrict__ b2,
    float* __restrict__ out, int B)
{
    const int warp = (blockIdx.x * blockDim.x + threadIdx.x) >> 5;
    const int lane = threadIdx.x & 31;
    if (warp >= B) return;

    const float4* x4 = (const float4*)(x + (size_t)warp * D);
    const float4* y4 = (const float4*)(y + (size_t)warp * D);

    float4 xv[4], yv[4];
    float d1 = 0.f, d2 = 0.f;
#pragma unroll
    for (int k = 0; k < 4; k++) {
        const int idx = lane + 32 * k;
        xv[k] = x4[idx];
        yv[k] = y4[idx];
        const float4 w1 = __ldg((const float4*)W1 + idx);
        const float4 w2 = __ldg((const float4*)W2 + idx);
        d1 += yv[k].x * w1.x + yv[k].y * w1.y + yv[k].z * w1.z + yv[k].w * w1.w;
        d2 += yv[k].x * w2.x + yv[k].y * w2.y + yv[k].z * w2.z + yv[k].w * w2.w;
    }
    const float scale = rsqrtf((float)D);
    const float s1 = wsum(d1) * scale;
    const float s2 = wsum(d2) * scale;

    float* out_x = out + (size_t)warp * D;
    float* out_y = out + (size_t)(B + warp) * D;

    // ---------------- side X: softmax(x*s1)*x + x, then LN(g1,b1) ----------
    {
        float m = -FLT_MAX;
#pragma unroll
        for (int k = 0; k < 4; k++) {
            m = fmaxf(m, fmaxf(fmaxf(xv[k].x * s1, xv[k].y * s1),
                               fmaxf(xv[k].z * s1, xv[k].w * s1)));
        }
        m = wmax(m);

        float4 ov[4];
        float esum = 0.f;
#pragma unroll
        for (int k = 0; k < 4; k++) {
            ov[k].x = __expf(xv[k].x * s1 - m);
            ov[k].y = __expf(xv[k].y * s1 - m);
            ov[k].z = __expf(xv[k].z * s1 - m);
            ov[k].w = __expf(xv[k].w * s1 - m);
            esum += ov[k].x + ov[k].y + ov[k].z + ov[k].w;
        }
        esum = wsum(esum);
        const float inv_es = 1.0f / esum;

        float sum = 0.f, sumsq = 0.f;
#pragma unroll
        for (int k = 0; k < 4; k++) {
            ov[k].x = ov[k].x * inv_es * xv[k].x + xv[k].x;
            ov[k].y = ov[k].y * inv_es * xv[k].y + xv[k].y;
            ov[k].z = ov[k].z * inv_es * xv[k].z + xv[k].z;
            ov[k].w = ov[k].w * inv_es * xv[k].w + xv[k].w;
            sum   += ov[k].x + ov[k].y + ov[k].z + ov[k].w;
            sumsq += ov[k].x * ov[k].x + ov[k].y * ov[k].y
                   + ov[k].z * ov[k].z + ov[k].w * ov[k].w;
        }
        sum = wsum(sum);
        sumsq = wsum(sumsq);
        const float mu = sum * (1.0f / D);
        const float var = sumsq * (1.0f / D) - mu * mu;
        const float rstd = rsqrtf(var + EPS);
#pragma unroll
        for (int k = 0; k < 4; k++) {
            const int idx = lane + 32 * k;
            const float4 gg = __ldg((const float4*)g1 + idx);
            const float4 bb = __ldg((const float4*)b1 + idx);
            float4 r;
            r.x = (ov[k].x - mu) * rstd * gg.x + bb.x;
            r.y = (ov[k].y - mu) * rstd * gg.y + bb.y;
            r.z = (ov[k].z - mu) * rstd * gg.z + bb.z;
            r.w = (ov[k].w - mu) * rstd * gg.w + bb.w;
            __stcs((float4*)out_x + idx, r);
        }
    }

    // ---------------- side Y: softmax(x*s2)*y + y, then LN(g2,b2) ----------
    {
        float m = -FLT_MAX;
#pragma unroll
        for (int k = 0; k < 4; k++) {
            m = fmaxf(m, fmaxf(fmaxf(xv[k].x * s2, xv[k].y * s2),
                               fmaxf(xv[k].z * s2, xv[k].w * s2)));
        }
        m = wmax(m);

        float4 ov[4];
        float esum = 0.f;
#pragma unroll
        for (int k = 0; k < 4; k++) {
            ov[k].x = __expf(xv[k].x * s2 - m);
            ov[k].y = __expf(xv[k].y * s2 - m);
            ov[k].z = __expf(xv[k].z * s2 - m);
            ov[k].w = __expf(xv[k].w * s2 - m);
            esum += ov[k].x + ov[k].y + ov[k].z + ov[k].w;
        }
        esum = wsum(esum);
        const float inv_es = 1.0f / esum;

        float sum = 0.f, sumsq = 0.f;
#pragma unroll
        for (int k = 0; k < 4; k++) {
            ov[k].x = ov[k].x * inv_es * yv[k].x + yv[k].x;
            ov[k].y = ov[k].y * inv_es * yv[k].y + yv[k].y;
            ov[k].z = ov[k].z * inv_es * yv[k].z + yv[k].z;
            ov[k].w = ov[k].w * inv_es * yv[k].w + yv[k].w;
            sum   += ov[k].x + ov[k].y + ov[k].z + ov[k].w;
            sumsq += ov[k].x * ov[k].x + ov[k].y * ov[k].y
                   + ov[k].z * ov[k].z + ov[k].w * ov[k].w;
        }
        sum = wsum(sum);
        sumsq = wsum(sumsq);
        const float mu = sum * (1.0f / D);
        const float var = sumsq * (1.0f / D) - mu * mu;
        const float rstd = rsqrtf(var + EPS);
#pragma unroll
        for (int k = 0; k < 4; k++) {
            const int idx = lane + 32 * k;
            const float4 gg = __ldg((const float4*)g2 + idx);
            const float4 bb = __ldg((const float4*)b2 + idx);
            float4 r;
            r.x = (ov[k].x - mu) * rstd * gg.x + bb.x;
            r.y = (ov[k].y - mu) * rstd * gg.y + bb.y;
            r.z = (ov[k].z - mu) * rstd * gg.z + bb.z;
            r.w = (ov[k].w - mu) * rstd * gg.w + bb.w;
            __stcs((float4*)out_y + idx, r);
        }
    }
}

extern "C" void kernel_launch(void* const* d_in, const int* in_sizes, int n_in,
                              void* d_out, int out_size) {
    const float* x  = (const float*)d_in[0];
    const float* y  = (const float*)d_in[1];
    const float* W1 = (const float*)d_in[2];
    const float* W2 = (const float*)d_in[3];
    const float* g1 = (const float*)d_in[4];
    const float* b1 = (const float*)d_in[5];
    const float* g2 = (const float*)d_in[6];
    const float* b2 = (const float*)d_in[7];
    float* out = (float*)d_out;

    const int B = in_sizes[0] / D;           // 65536
    const int threads = 256;                 // 8 rows per block
    const int rows_per_block = threads / 32;
    const int blocks = (B + rows_per_block - 1) / rows_per_block;
    simblock_kernel<<<blocks, threads>>>(x, y, W1, W2, g1, b1, g2, b2, out, B);
}